// round 13
// baseline (speedup 1.0000x reference)
#include <cuda_runtime.h>
#include <cuda_fp16.h>
#include <cstdint>
#include <cstddef>

#define BN_EPS 1e-5f
#define HROW 40      // smem row stride in halfs (80 B, 16B-aligned)

// dynamic smem (bytes): [0,512) rowIdx; [512,+20480) As x2; [20992,+20480) Bs x2
#define OFF_AS 512
#define OFF_BS 20992
#define SMEM_DYN (20992 + 20480)

#define STATS_G 1008   // grid for stats: 1008*256 divisible by C/4 for C in {128,192,224,512}
#define ELTW_G  1184   // grid for elementwise kernels

// ======================= static scratch (no allocs) =======================
__device__ float  g_acc [30000 * 512];
__device__ __half g_hA  [30000 * 512];
__device__ __half g_hB  [30000 * 512];
__device__ __half g_wth [13450240];     // transposed fp16 weights pool
__device__ float  g_stats[1024];        // [0,512) sum, [512,1024) sumsq
__device__ float  g_scale[512];
__device__ float  g_shift[512];

struct half2x2 { __half2 a, b; };       // 8-byte packed store unit

// ======================= helpers =========================================
__device__ __forceinline__ uint32_t smem_u32(const void* p) {
    uint32_t a;
    asm("{ .reg .u64 t; cvta.to.shared.u64 t, %1; cvt.u32.u64 %0, t; }" : "=r"(a) : "l"(p));
    return a;
}
__device__ __forceinline__ void mma_f16(float* d, const uint32_t* a, const uint32_t* b) {
    asm volatile(
        "mma.sync.aligned.m16n8k16.row.col.f32.f16.f16.f32 "
        "{%0,%1,%2,%3}, {%4,%5,%6,%7}, {%8,%9}, {%0,%1,%2,%3};"
        : "+f"(d[0]), "+f"(d[1]), "+f"(d[2]), "+f"(d[3])
        : "r"(a[0]), "r"(a[1]), "r"(a[2]), "r"(a[3]), "r"(b[0]), "r"(b[1]));
}
__device__ __forceinline__ void red_add_v4(float* p, float a, float b, float c, float d) {
    asm volatile("red.global.add.v4.f32 [%0], {%1, %2, %3, %4};"
                 :: "l"(p), "f"(a), "f"(b), "f"(c), "f"(d) : "memory");
}
__device__ __forceinline__ void cp_async16(uint32_t dst, const void* src, int szvalid) {
    asm volatile("cp.async.cg.shared.global [%0], [%1], 16, %2;"
                 :: "r"(dst), "l"(src), "r"(szvalid) : "memory");
}
#define CP_COMMIT()  asm volatile("cp.async.commit_group;" ::: "memory")
#define CP_WAIT(n)   asm volatile("cp.async.wait_group %0;" :: "n"(n) : "memory")

// ======================= fp16 tensor-core gather-GEMM-scatter =============
// (unchanged from R11 — passed at 1661us, ~90% tensor-pipe bound)
__global__ __launch_bounds__(256, 2) void mma_gs_kernel(
    const __half* __restrict__ A, const __half* __restrict__ WT,
    const int* __restrict__ in_idx, const int* __restrict__ out_idx,
    float* __restrict__ C, int M, int Cin, int Cout)
{
    extern __shared__ char sm[];
    int*      rowIdx = (int*)sm;
    uint32_t* AsW    = (uint32_t*)(sm + OFF_AS);
    uint32_t* BsW    = (uint32_t*)(sm + OFF_BS);
    const uint32_t bsU = smem_u32(sm) + OFF_BS;

    const int tid  = threadIdx.x;
    const int wid  = tid >> 5;
    const int lane = tid & 31;
    const int g8   = lane >> 2;
    const int t4   = lane & 3;

    const int k     = blockIdx.z;
    const int mBase = blockIdx.x * 128;
    const int n0    = blockIdx.y * 128;
    const __half* WTk = WT + (size_t)k * Cout * Cin;

    const int warpM = (wid >> 2) * 64;
    const int warpN = (wid & 3) * 32;

    if (tid < 128) {
        int g = mBase + tid;
        int ri = 0;
        if (g < M) ri = in_idx ? in_idx[(size_t)k * M + g] : g;
        rowIdx[tid] = ri;
    }
    __syncthreads();

    const __half* aptr[2];
    const __half* bptr[2];
    int bvalid[2];
#pragma unroll
    for (int s = 0; s < 2; ++s) {
        int gi = tid + s * 256;
        int row = gi >> 2, j = gi & 3;
        aptr[s] = A + (size_t)rowIdx[row] * Cin + 8 * j;
        int brow = n0 + row;
        bvalid[s] = (brow < Cout);
        bptr[s] = WTk + (size_t)(bvalid[s] ? brow : 0) * Cin + 8 * j;
    }

    float d[4][4][4];
#pragma unroll
    for (int mi = 0; mi < 4; mi++)
#pragma unroll
        for (int ni = 0; ni < 4; ni++)
#pragma unroll
            for (int r = 0; r < 4; r++) d[mi][ni][r] = 0.f;

    const int nc = (Cin + 31) >> 5;

    uint4 pav[2];
#pragma unroll
    for (int s = 0; s < 2; ++s) {
        int gi = tid + s * 256;
        int j = gi & 3;
        pav[s] = make_uint4(0u, 0u, 0u, 0u);
        if (8 * j < Cin) pav[s] = *(const uint4*)(aptr[s]);
    }
#pragma unroll
    for (int s = 0; s < 2; ++s) {
        int gi = tid + s * 256;
        int row = gi >> 2, j = gi & 3;
        int ok = (8 * j < Cin && bvalid[s]) ? 16 : 0;
        cp_async16(bsU + (uint32_t)(row * 80 + 16 * j), bptr[s], ok);
    }
    CP_COMMIT();

    for (int c = 0; c < nc; ++c) {
        const int st = c & 1;
        const int stoff = st * 128 * (HROW / 2);

#pragma unroll
        for (int s = 0; s < 2; ++s) {
            int gi = tid + s * 256;
            int row = gi >> 2, j = gi & 3;
            *(uint4*)&AsW[stoff + row * 20 + 4 * j] = pav[s];
        }

        if (c + 1 < nc) {
            const int c1 = (c + 1) << 5;
#pragma unroll
            for (int s = 0; s < 2; ++s) {
                int gi = tid + s * 256;
                int j = gi & 3;
                int col = c1 + 8 * j;
                pav[s] = make_uint4(0u, 0u, 0u, 0u);
                if (col < Cin) pav[s] = *(const uint4*)(aptr[s] + c1);
            }
        }

        CP_WAIT(0);
        __syncthreads();

        if (c + 1 < nc) {
            const int c1 = (c + 1) << 5;
#pragma unroll
            for (int s = 0; s < 2; ++s) {
                int gi = tid + s * 256;
                int row = gi >> 2, j = gi & 3;
                int ok = (c1 + 8 * j < Cin && bvalid[s]) ? 16 : 0;
                cp_async16(bsU + (uint32_t)((st ^ 1) * 10240 + row * 80 + 16 * j),
                           bptr[s] + c1, ok);
            }
            CP_COMMIT();
        }

        const uint32_t* AsB = AsW + stoff;
        const uint32_t* BsB = BsW + stoff;
#pragma unroll
        for (int kk = 0; kk < 2; ++kk) {
            const int kw = kk * 8;
            uint32_t a[4][4];
#pragma unroll
            for (int mi = 0; mi < 4; mi++) {
                int r = warpM + mi * 16 + g8;
                int w = r * 20 + kw + t4;
                a[mi][0] = AsB[w];
                a[mi][1] = AsB[w + 8 * 20];
                a[mi][2] = AsB[w + 4];
                a[mi][3] = AsB[w + 8 * 20 + 4];
            }
            uint32_t b[4][2];
#pragma unroll
            for (int ni = 0; ni < 4; ni++) {
                int n = warpN + ni * 8 + g8;
                int w = n * 20 + kw + t4;
                b[ni][0] = BsB[w];
                b[ni][1] = BsB[w + 4];
            }
#pragma unroll
            for (int mi = 0; mi < 4; mi++)
#pragma unroll
                for (int ni = 0; ni < 4; ni++)
                    mma_f16(d[mi][ni], a[mi], b[ni]);
        }
    }

#pragma unroll
    for (int mi = 0; mi < 4; mi++) {
        int r0 = mBase + warpM + mi * 16 + g8;
#pragma unroll
        for (int half = 0; half < 2; half++) {
            int rr = r0 + half * 8;
            size_t orow = 0;
            if (rr < M)
                orow = out_idx ? (size_t)out_idx[(size_t)k * M + rr] : (size_t)rr;
            float* crow = C + orow * Cout;
#pragma unroll
            for (int ni = 0; ni < 4; ni++) {
                float v0 = d[mi][ni][half * 2 + 0];
                float v1 = d[mi][ni][half * 2 + 1];
                float p0 = __shfl_xor_sync(0xffffffffu, v0, 1);
                float p1 = __shfl_xor_sync(0xffffffffu, v1, 1);
                if (rr < M && (t4 & 1) == 0) {
                    int col = n0 + warpN + ni * 8 + (t4 << 1);
                    if (col < Cout) {
                        if (out_idx) red_add_v4(crow + col, v0, v1, p0, p1);
                        else *(float4*)(crow + col) = make_float4(v0, v1, p0, p1);
                    }
                }
            }
        }
    }
}

// ===== weight transpose [K][Cin][Cout] -> [K][Cout][Cin], fp16-rounded ====
__global__ void transpose_kernel(const float* __restrict__ in, __half* __restrict__ out,
                                 int R, int Ccol)
{
    __shared__ float t[32][33];
    const size_t koff = (size_t)blockIdx.z * R * Ccol;
    const float* ink = in + koff;
    __half* outk = out + koff;
    int c0 = blockIdx.x * 32, r0 = blockIdx.y * 32;
    for (int i = threadIdx.y; i < 32; i += 8) {
        int r = r0 + i, c = c0 + threadIdx.x;
        t[i][threadIdx.x] = (r < R && c < Ccol) ? ink[(size_t)r * Ccol + c] : 0.f;
    }
    __syncthreads();
    for (int i = threadIdx.y; i < 32; i += 8) {
        int cc = c0 + i, rr = r0 + threadIdx.x;
        if (cc < Ccol && rr < R) outk[(size_t)cc * R + rr] = __float2half_rn(t[threadIdx.x][i]);
    }
}

// ============ f32 -> f16 vectorized convert (n4 = n/4 float4s) ===========
__global__ void cvt_kernel(const float4* __restrict__ in, half2x2* __restrict__ out, size_t n4)
{
    size_t stride = (size_t)gridDim.x * blockDim.x;
    for (size_t i = (size_t)blockIdx.x * blockDim.x + threadIdx.x; i < n4; i += stride) {
        float4 v = in[i];
        half2x2 o;
        o.a = __floats2half2_rn(v.x, v.y);
        o.b = __floats2half2_rn(v.z, v.w);
        out[i] = o;
    }
}

// ======== stats: per-thread fixed-channel register accumulation ==========
// REQUIRES: (gridDim.x * blockDim.x) % Cq == 0  (so channels stay fixed).
__global__ void stats_kernel(const float4* __restrict__ x4, size_t total4, int Cq,
                             float* __restrict__ stats /* [0,C) sum, [512,512+C) sq */)
{
    size_t idx0   = (size_t)blockIdx.x * blockDim.x + threadIdx.x;
    size_t stride = (size_t)gridDim.x * blockDim.x;
    float s0 = 0.f, s1 = 0.f, s2 = 0.f, s3 = 0.f;
    float q0 = 0.f, q1 = 0.f, q2 = 0.f, q3 = 0.f;
    for (size_t i = idx0; i < total4; i += stride) {
        float4 v = x4[i];
        s0 += v.x; q0 += v.x * v.x;
        s1 += v.y; q1 += v.y * v.y;
        s2 += v.z; q2 += v.z * v.z;
        s3 += v.w; q3 += v.w * v.w;
    }
    int c0 = (int)(idx0 % (size_t)Cq) * 4;
    atomicAdd(&stats[c0 + 0], s0);
    atomicAdd(&stats[c0 + 1], s1);
    atomicAdd(&stats[c0 + 2], s2);
    atomicAdd(&stats[c0 + 3], s3);
    atomicAdd(&stats[512 + c0 + 0], q0);
    atomicAdd(&stats[512 + c0 + 1], q1);
    atomicAdd(&stats[512 + c0 + 2], q2);
    atomicAdd(&stats[512 + c0 + 3], q3);
}

__global__ void bnparam_kernel(const float* __restrict__ stats,
                               const float* __restrict__ gamma, const float* __restrict__ beta,
                               int N, int C,
                               float* __restrict__ scale, float* __restrict__ shift)
{
    int c = blockIdx.x * blockDim.x + threadIdx.x;
    if (c < C) {
        float invN = 1.f / (float)N;
        float m = stats[c] * invN;
        float v = stats[512 + c] * invN - m * m;
        float sc = gamma[c] * rsqrtf(v + BN_EPS);
        scale[c] = sc;
        shift[c] = beta[c] - m * sc;
    }
}

// normalize+ReLU -> fp16 concat-strided buffer; vectorized float4 -> 2x half2
__global__ void bnapply_h_kernel(const float4* __restrict__ x4, size_t total4, int Cq,
                                 int ostride,
                                 const float* __restrict__ scale, const float* __restrict__ shift,
                                 __half* __restrict__ out)
{
    size_t stride = (size_t)gridDim.x * blockDim.x;
    for (size_t i = (size_t)blockIdx.x * blockDim.x + threadIdx.x; i < total4; i += stride) {
        float4 v = x4[i];
        int cq = (int)(i % (size_t)Cq);
        size_t r = i / (size_t)Cq;
        int c0 = cq * 4;
        float o0 = fmaxf(fmaf(v.x, scale[c0 + 0], shift[c0 + 0]), 0.f);
        float o1 = fmaxf(fmaf(v.y, scale[c0 + 1], shift[c0 + 1]), 0.f);
        float o2 = fmaxf(fmaf(v.z, scale[c0 + 2], shift[c0 + 2]), 0.f);
        float o3 = fmaxf(fmaf(v.w, scale[c0 + 3], shift[c0 + 3]), 0.f);
        half2x2 h;
        h.a = __floats2half2_rn(o0, o1);
        h.b = __floats2half2_rn(o2, o3);
        *(half2x2*)(out + r * (size_t)ostride + c0) = h;
    }
}

// final layer: normalize+ReLU in place (fp32), vectorized
__global__ void bnapply_f_kernel(float4* __restrict__ x4, size_t total4, int Cq,
                                 const float* __restrict__ scale, const float* __restrict__ shift)
{
    size_t stride = (size_t)gridDim.x * blockDim.x;
    for (size_t i = (size_t)blockIdx.x * blockDim.x + threadIdx.x; i < total4; i += stride) {
        float4 v = x4[i];
        int c0 = (int)(i % (size_t)Cq) * 4;
        v.x = fmaxf(fmaf(v.x, scale[c0 + 0], shift[c0 + 0]), 0.f);
        v.y = fmaxf(fmaf(v.y, scale[c0 + 1], shift[c0 + 1]), 0.f);
        v.z = fmaxf(fmaf(v.z, scale[c0 + 2], shift[c0 + 2]), 0.f);
        v.w = fmaxf(fmaf(v.w, scale[c0 + 3], shift[c0 + 3]), 0.f);
        x4[i] = v;
    }
}

// skip copy f32 -> f16 into concat-strided buffer; vectorized
__global__ void copyskip_kernel(const float4* __restrict__ f4, size_t total4, int Cfq,
                                int ostride, int coff, __half* __restrict__ out)
{
    size_t stride = (size_t)gridDim.x * blockDim.x;
    for (size_t i = (size_t)blockIdx.x * blockDim.x + threadIdx.x; i < total4; i += stride) {
        float4 v = f4[i];
        int c0 = (int)(i % (size_t)Cfq) * 4;
        size_t r = i / (size_t)Cfq;
        half2x2 h;
        h.a = __floats2half2_rn(v.x, v.y);
        h.b = __floats2half2_rn(v.z, v.w);
        *(half2x2*)(out + r * (size_t)ostride + coff + c0) = h;
    }
}

// ==========================================================================
extern "C" void kernel_launch(void* const* d_in, const int* in_sizes, int n_in,
                              void* d_out, int out_size)
{
    (void)in_sizes; (void)n_in; (void)out_size;

    const float* f0    = (const float*)d_in[0];
    const float* f1    = (const float*)d_in[1];
    const float* f2    = (const float*)d_in[2];
    const float* f3    = (const float*)d_in[3];
    const float* W_up2 = (const float*)d_in[4];
    const float* W_up1 = (const float*)d_in[5];
    const float* W_up0 = (const float*)d_in[6];
    const float* W_s0  = (const float*)d_in[7];
    const float* W_s1  = (const float*)d_in[8];
    const float* W_s2  = (const float*)d_in[9];
    const float* g_up2 = (const float*)d_in[10]; const float* b_up2 = (const float*)d_in[11];
    const float* g_up1 = (const float*)d_in[12]; const float* b_up1 = (const float*)d_in[13];
    const float* g_up0 = (const float*)d_in[14]; const float* b_up0 = (const float*)d_in[15];
    const float* g_s0  = (const float*)d_in[16]; const float* b_s0  = (const float*)d_in[17];
    const float* g_s1  = (const float*)d_in[18]; const float* b_s1  = (const float*)d_in[19];
    const float* g_s2  = (const float*)d_in[20]; const float* b_s2  = (const float*)d_in[21];
    const int* up2_in = (const int*)d_in[22]; const int* up2_out = (const int*)d_in[23];
    const int* up1_in = (const int*)d_in[24]; const int* up1_out = (const int*)d_in[25];
    const int* up0_in = (const int*)d_in[26]; const int* up0_out = (const int*)d_in[27];
    const int* sm0_in = (const int*)d_in[28]; const int* sm0_out = (const int*)d_in[29];
    const int* sm1_in = (const int*)d_in[30]; const int* sm1_out = (const int*)d_in[31];

    float *acc, *stats, *scale, *shift;
    __half *hA, *hB, *wth;
    cudaGetSymbolAddress((void**)&acc,   g_acc);
    cudaGetSymbolAddress((void**)&hA,    g_hA);
    cudaGetSymbolAddress((void**)&hB,    g_hB);
    cudaGetSymbolAddress((void**)&wth,   g_wth);
    cudaGetSymbolAddress((void**)&stats, g_stats);
    cudaGetSymbolAddress((void**)&scale, g_scale);
    cudaGetSymbolAddress((void**)&shift, g_shift);

    cudaFuncSetAttribute(mma_gs_kernel,
                         cudaFuncAttributeMaxDynamicSharedMemorySize, SMEM_DYN);

    const int N0 = 30000, N1 = 12000, N2 = 5000;
    const int K = 27;

    // --- transpose all weights into fp16 pool ---
    __half* wt_up2 = wth;
    __half* wt_up1 = wt_up2 + (size_t)27 * 128 * 128;
    __half* wt_up0 = wt_up1 + (size_t)27 * 192 * 192;
    __half* wt_s0  = wt_up0 + (size_t)27 * 224 * 224;
    __half* wt_s1  = wt_s0  + (size_t)27 * 240 * 512;
    __half* wt_s2  = wt_s1  + (size_t)27 * 512 * 512;

    auto tlaunch = [&](const float* W, __half* WT, int Cin, int Cout, int kk) {
        dim3 tg((Cout + 31) / 32, (Cin + 31) / 32, kk);
        transpose_kernel<<<tg, dim3(32, 8), 0, 0>>>(W, WT, Cin, Cout);
    };
    tlaunch(W_up2, wt_up2, 128, 128, K);
    tlaunch(W_up1, wt_up1, 192, 192, K);
    tlaunch(W_up0, wt_up0, 224, 224, K);
    tlaunch(W_s0,  wt_s0,  240, 512, K);
    tlaunch(W_s1,  wt_s1,  512, 512, K);
    tlaunch(W_s2,  wt_s2,  512, 512, 1);

    // f3 -> fp16 in hB (hB not written again until up1's output)
    cvt_kernel<<<ELTW_G, 256, 0, 0>>>((const float4*)f3, (half2x2*)hB, (size_t)2000 * 128 / 4);

    auto layer = [&](const __half* A, const __half* WT,
                     const int* ii, const int* oi,
                     int M, int Cin, int Cout, int Nout,
                     const float* gamma, const float* beta,
                     __half* outbuf, int ostride,       // fp16 output (or null for final)
                     float* foutbuf,                    // fp32 output (final layer)
                     const float* skip, int Cskip, int skip_N)
    {
        bool sparse = (oi != nullptr);
        float* dst = sparse ? acc : foutbuf;
        if (sparse)
            cudaMemsetAsync(acc, 0, (size_t)Nout * Cout * sizeof(float), 0);
        cudaMemsetAsync(stats, 0, 1024 * sizeof(float), 0);

        dim3 grid((M + 127) / 128, (Cout + 127) / 128, sparse ? K : 1);
        mma_gs_kernel<<<grid, 256, SMEM_DYN, 0>>>(A, WT, ii, oi, dst, M, Cin, Cout);

        size_t total4 = (size_t)Nout * Cout / 4;
        int Cq = Cout / 4;
        stats_kernel<<<STATS_G, 256, 0, 0>>>((const float4*)dst, total4, Cq, stats);
        bnparam_kernel<<<2, 256, 0, 0>>>(stats, gamma, beta, Nout, Cout, scale, shift);
        if (outbuf) {
            bnapply_h_kernel<<<ELTW_G, 256, 0, 0>>>((const float4*)dst, total4, Cq,
                                                    ostride, scale, shift, outbuf);
            if (skip)
                copyskip_kernel<<<ELTW_G, 256, 0, 0>>>((const float4*)skip,
                                                       (size_t)skip_N * Cskip / 4,
                                                       Cskip / 4, ostride, Cout, outbuf);
        } else {
            bnapply_f_kernel<<<ELTW_G, 256, 0, 0>>>((float4*)dst, total4, Cq, scale, shift);
        }
    };

    // up2: f3(h) -> N2 (Cout 128), concat f2(64) -> hA[5000,192]
    layer(hB, wt_up2, up2_in, up2_out, 1600, 128, 128, N2, g_up2, b_up2, hA, 192, nullptr, f2, 64, N2);
    // up1: hA -> N1 (Cout 192), concat f1(32) -> hB[12000,224]
    layer(hA, wt_up1, up1_in, up1_out, 4000, 192, 192, N1, g_up1, b_up1, hB, 224, nullptr, f1, 32, N1);
    // up0: hB -> N0 (Cout 224), concat f0(16) -> hA[30000,240]
    layer(hB, wt_up0, up0_in, up0_out, 10000, 224, 224, N0, g_up0, b_up0, hA, 240, nullptr, f0, 16, N0);
    // s0: hA[30000,240] -> N0 (Cout 512) -> hB
    layer(hA, wt_s0, sm0_in, sm0_out, 10000, 240, 512, N0, g_s0, b_s0, hB, 512, nullptr, nullptr, 0, 0);
    // s1: hB -> N0 (Cout 512) -> hA
    layer(hB, wt_s1, sm1_in, sm1_out, 10000, 512, 512, N0, g_s1, b_s1, hA, 512, nullptr, nullptr, 0, 0);
    // s2: dense GEMM hA @ W_s2 -> d_out (fp32), BN+ReLU in place
    layer(hA, wt_s2, nullptr, nullptr, N0, 512, 512, N0, g_s2, b_s2, nullptr, 512, (float*)d_out, nullptr, 0, 0);
}

// round 14
// speedup vs baseline: 2.0718x; 2.0718x over previous
#include <cuda_runtime.h>
#include <cuda_fp16.h>
#include <cstdint>
#include <cstddef>

#define BN_EPS 1e-5f
#define HROW 40      // smem row stride in halfs (80 B, 16B-aligned)

// dynamic smem (bytes): [0,512) rowIdx; [512,+20480) As x2; [20992,+20480) Bs x2
#define OFF_AS 512
#define OFF_BS 20992
#define SMEM_DYN (20992 + 20480)

#define ELTW_G  1184   // grid for elementwise kernels

// ======================= static scratch (no allocs) =======================
__device__ float  g_acc [30000 * 512];
__device__ __half g_hA  [30000 * 512];
__device__ __half g_hB  [30000 * 512];
__device__ __half g_wth [13450240];     // transposed fp16 weights pool
__device__ float  g_stats[1024];        // [0,512) sum, [512,1024) sumsq
__device__ float  g_scale[512];
__device__ float  g_shift[512];

struct half2x2 { __half2 a, b; };       // 8-byte packed store unit

// ======================= helpers =========================================
__device__ __forceinline__ uint32_t smem_u32(const void* p) {
    uint32_t a;
    asm("{ .reg .u64 t; cvta.to.shared.u64 t, %1; cvt.u32.u64 %0, t; }" : "=r"(a) : "l"(p));
    return a;
}
__device__ __forceinline__ void mma_f16(float* d, const uint32_t* a, const uint32_t* b) {
    asm volatile(
        "mma.sync.aligned.m16n8k16.row.col.f32.f16.f16.f32 "
        "{%0,%1,%2,%3}, {%4,%5,%6,%7}, {%8,%9}, {%0,%1,%2,%3};"
        : "+f"(d[0]), "+f"(d[1]), "+f"(d[2]), "+f"(d[3])
        : "r"(a[0]), "r"(a[1]), "r"(a[2]), "r"(a[3]), "r"(b[0]), "r"(b[1]));
}
__device__ __forceinline__ void red_add_v4(float* p, float a, float b, float c, float d) {
    asm volatile("red.global.add.v4.f32 [%0], {%1, %2, %3, %4};"
                 :: "l"(p), "f"(a), "f"(b), "f"(c), "f"(d) : "memory");
}
__device__ __forceinline__ void cp_async16(uint32_t dst, const void* src, int szvalid) {
    asm volatile("cp.async.cg.shared.global [%0], [%1], 16, %2;"
                 :: "r"(dst), "l"(src), "r"(szvalid) : "memory");
}
#define CP_COMMIT()  asm volatile("cp.async.commit_group;" ::: "memory")
#define CP_WAIT(n)   asm volatile("cp.async.wait_group %0;" :: "n"(n) : "memory")

// ======================= fp16 tensor-core gather-GEMM-scatter =============
// (unchanged from R11 — passed at 1661us, ~90% tensor-pipe bound)
__global__ __launch_bounds__(256, 2) void mma_gs_kernel(
    const __half* __restrict__ A, const __half* __restrict__ WT,
    const int* __restrict__ in_idx, const int* __restrict__ out_idx,
    float* __restrict__ C, int M, int Cin, int Cout)
{
    extern __shared__ char sm[];
    int*      rowIdx = (int*)sm;
    uint32_t* AsW    = (uint32_t*)(sm + OFF_AS);
    uint32_t* BsW    = (uint32_t*)(sm + OFF_BS);
    const uint32_t bsU = smem_u32(sm) + OFF_BS;

    const int tid  = threadIdx.x;
    const int wid  = tid >> 5;
    const int lane = tid & 31;
    const int g8   = lane >> 2;
    const int t4   = lane & 3;

    const int k     = blockIdx.z;
    const int mBase = blockIdx.x * 128;
    const int n0    = blockIdx.y * 128;
    const __half* WTk = WT + (size_t)k * Cout * Cin;

    const int warpM = (wid >> 2) * 64;
    const int warpN = (wid & 3) * 32;

    if (tid < 128) {
        int g = mBase + tid;
        int ri = 0;
        if (g < M) ri = in_idx ? in_idx[(size_t)k * M + g] : g;
        rowIdx[tid] = ri;
    }
    __syncthreads();

    const __half* aptr[2];
    const __half* bptr[2];
    int bvalid[2];
#pragma unroll
    for (int s = 0; s < 2; ++s) {
        int gi = tid + s * 256;
        int row = gi >> 2, j = gi & 3;
        aptr[s] = A + (size_t)rowIdx[row] * Cin + 8 * j;
        int brow = n0 + row;
        bvalid[s] = (brow < Cout);
        bptr[s] = WTk + (size_t)(bvalid[s] ? brow : 0) * Cin + 8 * j;
    }

    float d[4][4][4];
#pragma unroll
    for (int mi = 0; mi < 4; mi++)
#pragma unroll
        for (int ni = 0; ni < 4; ni++)
#pragma unroll
            for (int r = 0; r < 4; r++) d[mi][ni][r] = 0.f;

    const int nc = (Cin + 31) >> 5;

    uint4 pav[2];
#pragma unroll
    for (int s = 0; s < 2; ++s) {
        int gi = tid + s * 256;
        int j = gi & 3;
        pav[s] = make_uint4(0u, 0u, 0u, 0u);
        if (8 * j < Cin) pav[s] = *(const uint4*)(aptr[s]);
    }
#pragma unroll
    for (int s = 0; s < 2; ++s) {
        int gi = tid + s * 256;
        int row = gi >> 2, j = gi & 3;
        int ok = (8 * j < Cin && bvalid[s]) ? 16 : 0;
        cp_async16(bsU + (uint32_t)(row * 80 + 16 * j), bptr[s], ok);
    }
    CP_COMMIT();

    for (int c = 0; c < nc; ++c) {
        const int st = c & 1;
        const int stoff = st * 128 * (HROW / 2);

#pragma unroll
        for (int s = 0; s < 2; ++s) {
            int gi = tid + s * 256;
            int row = gi >> 2, j = gi & 3;
            *(uint4*)&AsW[stoff + row * 20 + 4 * j] = pav[s];
        }

        if (c + 1 < nc) {
            const int c1 = (c + 1) << 5;
#pragma unroll
            for (int s = 0; s < 2; ++s) {
                int gi = tid + s * 256;
                int j = gi & 3;
                int col = c1 + 8 * j;
                pav[s] = make_uint4(0u, 0u, 0u, 0u);
                if (col < Cin) pav[s] = *(const uint4*)(aptr[s] + c1);
            }
        }

        CP_WAIT(0);
        __syncthreads();

        if (c + 1 < nc) {
            const int c1 = (c + 1) << 5;
#pragma unroll
            for (int s = 0; s < 2; ++s) {
                int gi = tid + s * 256;
                int row = gi >> 2, j = gi & 3;
                int ok = (c1 + 8 * j < Cin && bvalid[s]) ? 16 : 0;
                cp_async16(bsU + (uint32_t)((st ^ 1) * 10240 + row * 80 + 16 * j),
                           bptr[s] + c1, ok);
            }
            CP_COMMIT();
        }

        const uint32_t* AsB = AsW + stoff;
        const uint32_t* BsB = BsW + stoff;
#pragma unroll
        for (int kk = 0; kk < 2; ++kk) {
            const int kw = kk * 8;
            uint32_t a[4][4];
#pragma unroll
            for (int mi = 0; mi < 4; mi++) {
                int r = warpM + mi * 16 + g8;
                int w = r * 20 + kw + t4;
                a[mi][0] = AsB[w];
                a[mi][1] = AsB[w + 8 * 20];
                a[mi][2] = AsB[w + 4];
                a[mi][3] = AsB[w + 8 * 20 + 4];
            }
            uint32_t b[4][2];
#pragma unroll
            for (int ni = 0; ni < 4; ni++) {
                int n = warpN + ni * 8 + g8;
                int w = n * 20 + kw + t4;
                b[ni][0] = BsB[w];
                b[ni][1] = BsB[w + 4];
            }
#pragma unroll
            for (int mi = 0; mi < 4; mi++)
#pragma unroll
                for (int ni = 0; ni < 4; ni++)
                    mma_f16(d[mi][ni], a[mi], b[ni]);
        }
    }

#pragma unroll
    for (int mi = 0; mi < 4; mi++) {
        int r0 = mBase + warpM + mi * 16 + g8;
#pragma unroll
        for (int half = 0; half < 2; half++) {
            int rr = r0 + half * 8;
            size_t orow = 0;
            if (rr < M)
                orow = out_idx ? (size_t)out_idx[(size_t)k * M + rr] : (size_t)rr;
            float* crow = C + orow * Cout;
#pragma unroll
            for (int ni = 0; ni < 4; ni++) {
                float v0 = d[mi][ni][half * 2 + 0];
                float v1 = d[mi][ni][half * 2 + 1];
                float p0 = __shfl_xor_sync(0xffffffffu, v0, 1);
                float p1 = __shfl_xor_sync(0xffffffffu, v1, 1);
                if (rr < M && (t4 & 1) == 0) {
                    int col = n0 + warpN + ni * 8 + (t4 << 1);
                    if (col < Cout) {
                        if (out_idx) red_add_v4(crow + col, v0, v1, p0, p1);
                        else *(float4*)(crow + col) = make_float4(v0, v1, p0, p1);
                    }
                }
            }
        }
    }
}

// ===== weight transpose [K][Cin][Cout] -> [K][Cout][Cin], fp16-rounded ====
__global__ void transpose_kernel(const float* __restrict__ in, __half* __restrict__ out,
                                 int R, int Ccol)
{
    __shared__ float t[32][33];
    const size_t koff = (size_t)blockIdx.z * R * Ccol;
    const float* ink = in + koff;
    __half* outk = out + koff;
    int c0 = blockIdx.x * 32, r0 = blockIdx.y * 32;
    for (int i = threadIdx.y; i < 32; i += 8) {
        int r = r0 + i, c = c0 + threadIdx.x;
        t[i][threadIdx.x] = (r < R && c < Ccol) ? ink[(size_t)r * Ccol + c] : 0.f;
    }
    __syncthreads();
    for (int i = threadIdx.y; i < 32; i += 8) {
        int cc = c0 + i, rr = r0 + threadIdx.x;
        if (cc < Ccol && rr < R) outk[(size_t)cc * R + rr] = __float2half_rn(t[threadIdx.x][i]);
    }
}

// ============ f32 -> f16 vectorized convert (n4 = n/4 float4s) ===========
__global__ void cvt_kernel(const float4* __restrict__ in, half2x2* __restrict__ out, size_t n4)
{
    size_t stride = (size_t)gridDim.x * blockDim.x;
    for (size_t i = (size_t)blockIdx.x * blockDim.x + threadIdx.x; i < n4; i += stride) {
        float4 v = in[i];
        half2x2 o;
        o.a = __floats2half2_rn(v.x, v.y);
        o.b = __floats2half2_rn(v.z, v.w);
        out[i] = o;
    }
}

// ==== stats: R11 shared-atomic version (known good at 1661us) ============
__global__ void stats_kernel(const float* __restrict__ x, size_t total, int C,
                             float* __restrict__ stats /* [0,C) sum, [512,512+C) sq */)
{
    extern __shared__ float s[];
    for (int i = threadIdx.x; i < 2 * C; i += blockDim.x) s[i] = 0.f;
    __syncthreads();
    for (size_t i = (size_t)blockIdx.x * blockDim.x + threadIdx.x; i < total;
         i += (size_t)gridDim.x * blockDim.x) {
        float v = x[i];
        int c = (int)(i % (size_t)C);
        atomicAdd(&s[c], v);
        atomicAdd(&s[C + c], v * v);
    }
    __syncthreads();
    for (int c = threadIdx.x; c < C; c += blockDim.x) {
        atomicAdd(&stats[c], s[c]);
        atomicAdd(&stats[512 + c], s[C + c]);
    }
}

__global__ void bnparam_kernel(const float* __restrict__ stats,
                               const float* __restrict__ gamma, const float* __restrict__ beta,
                               int N, int C,
                               float* __restrict__ scale, float* __restrict__ shift)
{
    int c = blockIdx.x * blockDim.x + threadIdx.x;
    if (c < C) {
        float invN = 1.f / (float)N;
        float m = stats[c] * invN;
        float v = stats[512 + c] * invN - m * m;
        float sc = gamma[c] * rsqrtf(v + BN_EPS);
        scale[c] = sc;
        shift[c] = beta[c] - m * sc;
    }
}

// normalize+ReLU -> fp16 concat-strided buffer; vectorized float4 -> 2x half2
__global__ void bnapply_h_kernel(const float4* __restrict__ x4, size_t total4, int Cq,
                                 int ostride,
                                 const float* __restrict__ scale, const float* __restrict__ shift,
                                 __half* __restrict__ out)
{
    size_t stride = (size_t)gridDim.x * blockDim.x;
    for (size_t i = (size_t)blockIdx.x * blockDim.x + threadIdx.x; i < total4; i += stride) {
        float4 v = x4[i];
        int cq = (int)(i % (size_t)Cq);
        size_t r = i / (size_t)Cq;
        int c0 = cq * 4;
        float o0 = fmaxf(fmaf(v.x, scale[c0 + 0], shift[c0 + 0]), 0.f);
        float o1 = fmaxf(fmaf(v.y, scale[c0 + 1], shift[c0 + 1]), 0.f);
        float o2 = fmaxf(fmaf(v.z, scale[c0 + 2], shift[c0 + 2]), 0.f);
        float o3 = fmaxf(fmaf(v.w, scale[c0 + 3], shift[c0 + 3]), 0.f);
        half2x2 h;
        h.a = __floats2half2_rn(o0, o1);
        h.b = __floats2half2_rn(o2, o3);
        *(half2x2*)(out + r * (size_t)ostride + c0) = h;
    }
}

// final layer: normalize+ReLU in place (fp32), vectorized
__global__ void bnapply_f_kernel(float4* __restrict__ x4, size_t total4, int Cq,
                                 const float* __restrict__ scale, const float* __restrict__ shift)
{
    size_t stride = (size_t)gridDim.x * blockDim.x;
    for (size_t i = (size_t)blockIdx.x * blockDim.x + threadIdx.x; i < total4; i += stride) {
        float4 v = x4[i];
        int c0 = (int)(i % (size_t)Cq) * 4;
        v.x = fmaxf(fmaf(v.x, scale[c0 + 0], shift[c0 + 0]), 0.f);
        v.y = fmaxf(fmaf(v.y, scale[c0 + 1], shift[c0 + 1]), 0.f);
        v.z = fmaxf(fmaf(v.z, scale[c0 + 2], shift[c0 + 2]), 0.f);
        v.w = fmaxf(fmaf(v.w, scale[c0 + 3], shift[c0 + 3]), 0.f);
        x4[i] = v;
    }
}

// skip copy f32 -> f16 into concat-strided buffer; vectorized
__global__ void copyskip_kernel(const float4* __restrict__ f4, size_t total4, int Cfq,
                                int ostride, int coff, __half* __restrict__ out)
{
    size_t stride = (size_t)gridDim.x * blockDim.x;
    for (size_t i = (size_t)blockIdx.x * blockDim.x + threadIdx.x; i < total4; i += stride) {
        float4 v = f4[i];
        int c0 = (int)(i % (size_t)Cfq) * 4;
        size_t r = i / (size_t)Cfq;
        half2x2 h;
        h.a = __floats2half2_rn(v.x, v.y);
        h.b = __floats2half2_rn(v.z, v.w);
        *(half2x2*)(out + r * (size_t)ostride + coff + c0) = h;
    }
}

// ==========================================================================
extern "C" void kernel_launch(void* const* d_in, const int* in_sizes, int n_in,
                              void* d_out, int out_size)
{
    (void)in_sizes; (void)n_in; (void)out_size;

    const float* f0    = (const float*)d_in[0];
    const float* f1    = (const float*)d_in[1];
    const float* f2    = (const float*)d_in[2];
    const float* f3    = (const float*)d_in[3];
    const float* W_up2 = (const float*)d_in[4];
    const float* W_up1 = (const float*)d_in[5];
    const float* W_up0 = (const float*)d_in[6];
    const float* W_s0  = (const float*)d_in[7];
    const float* W_s1  = (const float*)d_in[8];
    const float* W_s2  = (const float*)d_in[9];
    const float* g_up2 = (const float*)d_in[10]; const float* b_up2 = (const float*)d_in[11];
    const float* g_up1 = (const float*)d_in[12]; const float* b_up1 = (const float*)d_in[13];
    const float* g_up0 = (const float*)d_in[14]; const float* b_up0 = (const float*)d_in[15];
    const float* g_s0  = (const float*)d_in[16]; const float* b_s0  = (const float*)d_in[17];
    const float* g_s1  = (const float*)d_in[18]; const float* b_s1  = (const float*)d_in[19];
    const float* g_s2  = (const float*)d_in[20]; const float* b_s2  = (const float*)d_in[21];
    const int* up2_in = (const int*)d_in[22]; const int* up2_out = (const int*)d_in[23];
    const int* up1_in = (const int*)d_in[24]; const int* up1_out = (const int*)d_in[25];
    const int* up0_in = (const int*)d_in[26]; const int* up0_out = (const int*)d_in[27];
    const int* sm0_in = (const int*)d_in[28]; const int* sm0_out = (const int*)d_in[29];
    const int* sm1_in = (const int*)d_in[30]; const int* sm1_out = (const int*)d_in[31];

    float *acc, *stats, *scale, *shift;
    __half *hA, *hB, *wth;
    cudaGetSymbolAddress((void**)&acc,   g_acc);
    cudaGetSymbolAddress((void**)&hA,    g_hA);
    cudaGetSymbolAddress((void**)&hB,    g_hB);
    cudaGetSymbolAddress((void**)&wth,   g_wth);
    cudaGetSymbolAddress((void**)&stats, g_stats);
    cudaGetSymbolAddress((void**)&scale, g_scale);
    cudaGetSymbolAddress((void**)&shift, g_shift);

    cudaFuncSetAttribute(mma_gs_kernel,
                         cudaFuncAttributeMaxDynamicSharedMemorySize, SMEM_DYN);

    const int N0 = 30000, N1 = 12000, N2 = 5000;
    const int K = 27;

    // --- transpose all weights into fp16 pool ---
    __half* wt_up2 = wth;
    __half* wt_up1 = wt_up2 + (size_t)27 * 128 * 128;
    __half* wt_up0 = wt_up1 + (size_t)27 * 192 * 192;
    __half* wt_s0  = wt_up0 + (size_t)27 * 224 * 224;
    __half* wt_s1  = wt_s0  + (size_t)27 * 240 * 512;
    __half* wt_s2  = wt_s1  + (size_t)27 * 512 * 512;

    auto tlaunch = [&](const float* W, __half* WT, int Cin, int Cout, int kk) {
        dim3 tg((Cout + 31) / 32, (Cin + 31) / 32, kk);
        transpose_kernel<<<tg, dim3(32, 8), 0, 0>>>(W, WT, Cin, Cout);
    };
    tlaunch(W_up2, wt_up2, 128, 128, K);
    tlaunch(W_up1, wt_up1, 192, 192, K);
    tlaunch(W_up0, wt_up0, 224, 224, K);
    tlaunch(W_s0,  wt_s0,  240, 512, K);
    tlaunch(W_s1,  wt_s1,  512, 512, K);
    tlaunch(W_s2,  wt_s2,  512, 512, 1);

    // f3 -> fp16 in hB (hB not written again until up1's output)
    cvt_kernel<<<ELTW_G, 256, 0, 0>>>((const float4*)f3, (half2x2*)hB, (size_t)2000 * 128 / 4);

    auto layer = [&](const __half* A, const __half* WT,
                     const int* ii, const int* oi,
                     int M, int Cin, int Cout, int Nout,
                     const float* gamma, const float* beta,
                     __half* outbuf, int ostride,       // fp16 output (or null for final)
                     float* foutbuf,                    // fp32 output (final layer)
                     const float* skip, int Cskip, int skip_N)
    {
        bool sparse = (oi != nullptr);
        float* dst = sparse ? acc : foutbuf;
        if (sparse)
            cudaMemsetAsync(acc, 0, (size_t)Nout * Cout * sizeof(float), 0);
        cudaMemsetAsync(stats, 0, 1024 * sizeof(float), 0);

        dim3 grid((M + 127) / 128, (Cout + 127) / 128, sparse ? K : 1);
        mma_gs_kernel<<<grid, 256, SMEM_DYN, 0>>>(A, WT, ii, oi, dst, M, Cin, Cout);

        size_t total  = (size_t)Nout * Cout;
        size_t total4 = total / 4;
        int Cq = Cout / 4;
        stats_kernel<<<592, 256, 2 * Cout * sizeof(float), 0>>>(dst, total, Cout, stats);
        bnparam_kernel<<<2, 256, 0, 0>>>(stats, gamma, beta, Nout, Cout, scale, shift);
        if (outbuf) {
            bnapply_h_kernel<<<ELTW_G, 256, 0, 0>>>((const float4*)dst, total4, Cq,
                                                    ostride, scale, shift, outbuf);
            if (skip)
                copyskip_kernel<<<ELTW_G, 256, 0, 0>>>((const float4*)skip,
                                                       (size_t)skip_N * Cskip / 4,
                                                       Cskip / 4, ostride, Cout, outbuf);
        } else {
            bnapply_f_kernel<<<ELTW_G, 256, 0, 0>>>((float4*)dst, total4, Cq, scale, shift);
        }
    };

    // up2: f3(h) -> N2 (Cout 128), concat f2(64) -> hA[5000,192]
    layer(hB, wt_up2, up2_in, up2_out, 1600, 128, 128, N2, g_up2, b_up2, hA, 192, nullptr, f2, 64, N2);
    // up1: hA -> N1 (Cout 192), concat f1(32) -> hB[12000,224]
    layer(hA, wt_up1, up1_in, up1_out, 4000, 192, 192, N1, g_up1, b_up1, hB, 224, nullptr, f1, 32, N1);
    // up0: hB -> N0 (Cout 224), concat f0(16) -> hA[30000,240]
    layer(hB, wt_up0, up0_in, up0_out, 10000, 224, 224, N0, g_up0, b_up0, hA, 240, nullptr, f0, 16, N0);
    // s0: hA[30000,240] -> N0 (Cout 512) -> hB
    layer(hA, wt_s0, sm0_in, sm0_out, 10000, 240, 512, N0, g_s0, b_s0, hB, 512, nullptr, nullptr, 0, 0);
    // s1: hB -> N0 (Cout 512) -> hA
    layer(hB, wt_s1, sm1_in, sm1_out, 10000, 512, 512, N0, g_s1, b_s1, hA, 512, nullptr, nullptr, 0, 0);
    // s2: dense GEMM hA @ W_s2 -> d_out (fp32), BN+ReLU in place
    layer(hA, wt_s2, nullptr, nullptr, N0, 512, 512, N0, g_s2, b_s2, nullptr, 512, (float*)d_out, nullptr, 0, 0);
}

// round 15
// speedup vs baseline: 2.2511x; 1.0865x over previous
#include <cuda_runtime.h>
#include <cuda_fp16.h>
#include <cstdint>
#include <cstddef>

#define BN_EPS 1e-5f
#define HROW 40      // smem row stride in halfs (80 B, 16B-aligned)

// dynamic smem (bytes): [0,512) rowIdx; [512,+20480) As x2; [20992,+20480) Bs x2
#define OFF_AS 512
#define OFF_BS 20992
#define SMEM_DYN (20992 + 20480)

#define ELTW_G  1184   // grid for elementwise kernels
#define STATS_G 588    // 588*256 = 150528, divisible by Cq for Cq in {32,48,56,128}

// ======================= static scratch (no allocs) =======================
__device__ float  g_acc [30000 * 512];
__device__ __half g_hA  [30000 * 512];
__device__ __half g_hB  [30000 * 512];
__device__ __half g_wth [13450240];     // transposed fp16 weights pool
__device__ float  g_stats[1024];        // [0,512) sum, [512,1024) sumsq
__device__ float  g_scale[512];
__device__ float  g_shift[512];

struct half2x2 { __half2 a, b; };       // 8-byte packed store unit

// ======================= helpers =========================================
__device__ __forceinline__ uint32_t smem_u32(const void* p) {
    uint32_t a;
    asm("{ .reg .u64 t; cvta.to.shared.u64 t, %1; cvt.u32.u64 %0, t; }" : "=r"(a) : "l"(p));
    return a;
}
__device__ __forceinline__ void mma_f16(float* d, const uint32_t* a, const uint32_t* b) {
    asm volatile(
        "mma.sync.aligned.m16n8k16.row.col.f32.f16.f16.f32 "
        "{%0,%1,%2,%3}, {%4,%5,%6,%7}, {%8,%9}, {%0,%1,%2,%3};"
        : "+f"(d[0]), "+f"(d[1]), "+f"(d[2]), "+f"(d[3])
        : "r"(a[0]), "r"(a[1]), "r"(a[2]), "r"(a[3]), "r"(b[0]), "r"(b[1]));
}
__device__ __forceinline__ void red_add_v4(float* p, float a, float b, float c, float d) {
    asm volatile("red.global.add.v4.f32 [%0], {%1, %2, %3, %4};"
                 :: "l"(p), "f"(a), "f"(b), "f"(c), "f"(d) : "memory");
}
__device__ __forceinline__ void cp_async16(uint32_t dst, const void* src, int szvalid) {
    asm volatile("cp.async.cg.shared.global [%0], [%1], 16, %2;"
                 :: "r"(dst), "l"(src), "r"(szvalid) : "memory");
}
#define CP_COMMIT()  asm volatile("cp.async.commit_group;" ::: "memory")
#define CP_WAIT(n)   asm volatile("cp.async.wait_group %0;" :: "n"(n) : "memory")

// ======================= fp16 tensor-core gather-GEMM-scatter =============
// (unchanged — proven at 1595us, ~90% tensor-pipe bound)
__global__ __launch_bounds__(256, 2) void mma_gs_kernel(
    const __half* __restrict__ A, const __half* __restrict__ WT,
    const int* __restrict__ in_idx, const int* __restrict__ out_idx,
    float* __restrict__ C, int M, int Cin, int Cout)
{
    extern __shared__ char sm[];
    int*      rowIdx = (int*)sm;
    uint32_t* AsW    = (uint32_t*)(sm + OFF_AS);
    uint32_t* BsW    = (uint32_t*)(sm + OFF_BS);
    const uint32_t bsU = smem_u32(sm) + OFF_BS;

    const int tid  = threadIdx.x;
    const int wid  = tid >> 5;
    const int lane = tid & 31;
    const int g8   = lane >> 2;
    const int t4   = lane & 3;

    const int k     = blockIdx.z;
    const int mBase = blockIdx.x * 128;
    const int n0    = blockIdx.y * 128;
    const __half* WTk = WT + (size_t)k * Cout * Cin;

    const int warpM = (wid >> 2) * 64;
    const int warpN = (wid & 3) * 32;

    if (tid < 128) {
        int g = mBase + tid;
        int ri = 0;
        if (g < M) ri = in_idx ? in_idx[(size_t)k * M + g] : g;
        rowIdx[tid] = ri;
    }
    __syncthreads();

    const __half* aptr[2];
    const __half* bptr[2];
    int bvalid[2];
#pragma unroll
    for (int s = 0; s < 2; ++s) {
        int gi = tid + s * 256;
        int row = gi >> 2, j = gi & 3;
        aptr[s] = A + (size_t)rowIdx[row] * Cin + 8 * j;
        int brow = n0 + row;
        bvalid[s] = (brow < Cout);
        bptr[s] = WTk + (size_t)(bvalid[s] ? brow : 0) * Cin + 8 * j;
    }

    float d[4][4][4];
#pragma unroll
    for (int mi = 0; mi < 4; mi++)
#pragma unroll
        for (int ni = 0; ni < 4; ni++)
#pragma unroll
            for (int r = 0; r < 4; r++) d[mi][ni][r] = 0.f;

    const int nc = (Cin + 31) >> 5;

    uint4 pav[2];
#pragma unroll
    for (int s = 0; s < 2; ++s) {
        int gi = tid + s * 256;
        int j = gi & 3;
        pav[s] = make_uint4(0u, 0u, 0u, 0u);
        if (8 * j < Cin) pav[s] = *(const uint4*)(aptr[s]);
    }
#pragma unroll
    for (int s = 0; s < 2; ++s) {
        int gi = tid + s * 256;
        int row = gi >> 2, j = gi & 3;
        int ok = (8 * j < Cin && bvalid[s]) ? 16 : 0;
        cp_async16(bsU + (uint32_t)(row * 80 + 16 * j), bptr[s], ok);
    }
    CP_COMMIT();

    for (int c = 0; c < nc; ++c) {
        const int st = c & 1;
        const int stoff = st * 128 * (HROW / 2);

#pragma unroll
        for (int s = 0; s < 2; ++s) {
            int gi = tid + s * 256;
            int row = gi >> 2, j = gi & 3;
            *(uint4*)&AsW[stoff + row * 20 + 4 * j] = pav[s];
        }

        if (c + 1 < nc) {
            const int c1 = (c + 1) << 5;
#pragma unroll
            for (int s = 0; s < 2; ++s) {
                int gi = tid + s * 256;
                int j = gi & 3;
                int col = c1 + 8 * j;
                pav[s] = make_uint4(0u, 0u, 0u, 0u);
                if (col < Cin) pav[s] = *(const uint4*)(aptr[s] + c1);
            }
        }

        CP_WAIT(0);
        __syncthreads();

        if (c + 1 < nc) {
            const int c1 = (c + 1) << 5;
#pragma unroll
            for (int s = 0; s < 2; ++s) {
                int gi = tid + s * 256;
                int row = gi >> 2, j = gi & 3;
                int ok = (c1 + 8 * j < Cin && bvalid[s]) ? 16 : 0;
                cp_async16(bsU + (uint32_t)((st ^ 1) * 10240 + row * 80 + 16 * j),
                           bptr[s] + c1, ok);
            }
            CP_COMMIT();
        }

        const uint32_t* AsB = AsW + stoff;
        const uint32_t* BsB = BsW + stoff;
#pragma unroll
        for (int kk = 0; kk < 2; ++kk) {
            const int kw = kk * 8;
            uint32_t a[4][4];
#pragma unroll
            for (int mi = 0; mi < 4; mi++) {
                int r = warpM + mi * 16 + g8;
                int w = r * 20 + kw + t4;
                a[mi][0] = AsB[w];
                a[mi][1] = AsB[w + 8 * 20];
                a[mi][2] = AsB[w + 4];
                a[mi][3] = AsB[w + 8 * 20 + 4];
            }
            uint32_t b[4][2];
#pragma unroll
            for (int ni = 0; ni < 4; ni++) {
                int n = warpN + ni * 8 + g8;
                int w = n * 20 + kw + t4;
                b[ni][0] = BsB[w];
                b[ni][1] = BsB[w + 4];
            }
#pragma unroll
            for (int mi = 0; mi < 4; mi++)
#pragma unroll
                for (int ni = 0; ni < 4; ni++)
                    mma_f16(d[mi][ni], a[mi], b[ni]);
        }
    }

#pragma unroll
    for (int mi = 0; mi < 4; mi++) {
        int r0 = mBase + warpM + mi * 16 + g8;
#pragma unroll
        for (int half = 0; half < 2; half++) {
            int rr = r0 + half * 8;
            size_t orow = 0;
            if (rr < M)
                orow = out_idx ? (size_t)out_idx[(size_t)k * M + rr] : (size_t)rr;
            float* crow = C + orow * Cout;
#pragma unroll
            for (int ni = 0; ni < 4; ni++) {
                float v0 = d[mi][ni][half * 2 + 0];
                float v1 = d[mi][ni][half * 2 + 1];
                float p0 = __shfl_xor_sync(0xffffffffu, v0, 1);
                float p1 = __shfl_xor_sync(0xffffffffu, v1, 1);
                if (rr < M && (t4 & 1) == 0) {
                    int col = n0 + warpN + ni * 8 + (t4 << 1);
                    if (col < Cout) {
                        if (out_idx) red_add_v4(crow + col, v0, v1, p0, p1);
                        else *(float4*)(crow + col) = make_float4(v0, v1, p0, p1);
                    }
                }
            }
        }
    }
}

// ===== weight transpose [K][Cin][Cout] -> [K][Cout][Cin], fp16-rounded ====
__global__ void transpose_kernel(const float* __restrict__ in, __half* __restrict__ out,
                                 int R, int Ccol)
{
    __shared__ float t[32][33];
    const size_t koff = (size_t)blockIdx.z * R * Ccol;
    const float* ink = in + koff;
    __half* outk = out + koff;
    int c0 = blockIdx.x * 32, r0 = blockIdx.y * 32;
    for (int i = threadIdx.y; i < 32; i += 8) {
        int r = r0 + i, c = c0 + threadIdx.x;
        t[i][threadIdx.x] = (r < R && c < Ccol) ? ink[(size_t)r * Ccol + c] : 0.f;
    }
    __syncthreads();
    for (int i = threadIdx.y; i < 32; i += 8) {
        int cc = c0 + i, rr = r0 + threadIdx.x;
        if (cc < Ccol && rr < R) outk[(size_t)cc * R + rr] = __float2half_rn(t[threadIdx.x][i]);
    }
}

// ============ f32 -> f16 vectorized convert (n4 = n/4 float4s) ===========
__global__ void cvt_kernel(const float4* __restrict__ in, half2x2* __restrict__ out, size_t n4)
{
    size_t stride = (size_t)gridDim.x * blockDim.x;
    for (size_t i = (size_t)blockIdx.x * blockDim.x + threadIdx.x; i < n4; i += stride) {
        float4 v = in[i];
        half2x2 o;
        o.a = __floats2half2_rn(v.x, v.y);
        o.b = __floats2half2_rn(v.z, v.w);
        out[i] = o;
    }
}

// ==== stats v3: register accumulation (fixed channels) + shared flush ====
// REQUIRES: (gridDim.x * blockDim.x) % Cq == 0  -> channels loop-invariant.
// Main loop: pure float4 read stream. Flush: 8 shared atomics per thread
// (once), then the R11-proven per-block global flush (gridDim.x * 2C ATOMG).
__global__ void stats_kernel(const float4* __restrict__ x4, size_t total4, int Cq,
                             float* __restrict__ stats /* [0,C) sum, [512,512+C) sq */)
{
    extern __shared__ float s[];  // 2*C floats
    const int C = Cq * 4;
    size_t idx0   = (size_t)blockIdx.x * blockDim.x + threadIdx.x;
    size_t stride = (size_t)gridDim.x * blockDim.x;
    float s0 = 0.f, s1 = 0.f, s2 = 0.f, s3 = 0.f;
    float q0 = 0.f, q1 = 0.f, q2 = 0.f, q3 = 0.f;
    for (size_t i = idx0; i < total4; i += stride) {
        float4 v = x4[i];
        s0 += v.x; q0 += v.x * v.x;
        s1 += v.y; q1 += v.y * v.y;
        s2 += v.z; q2 += v.z * v.z;
        s3 += v.w; q3 += v.w * v.w;
    }
    for (int i = threadIdx.x; i < 2 * C; i += blockDim.x) s[i] = 0.f;
    __syncthreads();
    int c0 = (int)(idx0 % (size_t)Cq) * 4;
    atomicAdd(&s[c0 + 0], s0);
    atomicAdd(&s[c0 + 1], s1);
    atomicAdd(&s[c0 + 2], s2);
    atomicAdd(&s[c0 + 3], s3);
    atomicAdd(&s[C + c0 + 0], q0);
    atomicAdd(&s[C + c0 + 1], q1);
    atomicAdd(&s[C + c0 + 2], q2);
    atomicAdd(&s[C + c0 + 3], q3);
    __syncthreads();
    for (int c = threadIdx.x; c < C; c += blockDim.x) {
        atomicAdd(&stats[c], s[c]);
        atomicAdd(&stats[512 + c], s[C + c]);
    }
}

__global__ void bnparam_kernel(const float* __restrict__ stats,
                               const float* __restrict__ gamma, const float* __restrict__ beta,
                               int N, int C,
                               float* __restrict__ scale, float* __restrict__ shift)
{
    int c = blockIdx.x * blockDim.x + threadIdx.x;
    if (c < C) {
        float invN = 1.f / (float)N;
        float m = stats[c] * invN;
        float v = stats[512 + c] * invN - m * m;
        float sc = gamma[c] * rsqrtf(v + BN_EPS);
        scale[c] = sc;
        shift[c] = beta[c] - m * sc;
    }
}

// normalize+ReLU -> fp16 concat-strided buffer; vectorized float4 -> 2x half2
__global__ void bnapply_h_kernel(const float4* __restrict__ x4, size_t total4, int Cq,
                                 int ostride,
                                 const float* __restrict__ scale, const float* __restrict__ shift,
                                 __half* __restrict__ out)
{
    size_t stride = (size_t)gridDim.x * blockDim.x;
    for (size_t i = (size_t)blockIdx.x * blockDim.x + threadIdx.x; i < total4; i += stride) {
        float4 v = x4[i];
        int cq = (int)(i % (size_t)Cq);
        size_t r = i / (size_t)Cq;
        int c0 = cq * 4;
        float o0 = fmaxf(fmaf(v.x, scale[c0 + 0], shift[c0 + 0]), 0.f);
        float o1 = fmaxf(fmaf(v.y, scale[c0 + 1], shift[c0 + 1]), 0.f);
        float o2 = fmaxf(fmaf(v.z, scale[c0 + 2], shift[c0 + 2]), 0.f);
        float o3 = fmaxf(fmaf(v.w, scale[c0 + 3], shift[c0 + 3]), 0.f);
        half2x2 h;
        h.a = __floats2half2_rn(o0, o1);
        h.b = __floats2half2_rn(o2, o3);
        *(half2x2*)(out + r * (size_t)ostride + c0) = h;
    }
}

// final layer: normalize+ReLU in place (fp32), vectorized
__global__ void bnapply_f_kernel(float4* __restrict__ x4, size_t total4, int Cq,
                                 const float* __restrict__ scale, const float* __restrict__ shift)
{
    size_t stride = (size_t)gridDim.x * blockDim.x;
    for (size_t i = (size_t)blockIdx.x * blockDim.x + threadIdx.x; i < total4; i += stride) {
        float4 v = x4[i];
        int c0 = (int)(i % (size_t)Cq) * 4;
        v.x = fmaxf(fmaf(v.x, scale[c0 + 0], shift[c0 + 0]), 0.f);
        v.y = fmaxf(fmaf(v.y, scale[c0 + 1], shift[c0 + 1]), 0.f);
        v.z = fmaxf(fmaf(v.z, scale[c0 + 2], shift[c0 + 2]), 0.f);
        v.w = fmaxf(fmaf(v.w, scale[c0 + 3], shift[c0 + 3]), 0.f);
        x4[i] = v;
    }
}

// skip copy f32 -> f16 into concat-strided buffer; vectorized
__global__ void copyskip_kernel(const float4* __restrict__ f4, size_t total4, int Cfq,
                                int ostride, int coff, __half* __restrict__ out)
{
    size_t stride = (size_t)gridDim.x * blockDim.x;
    for (size_t i = (size_t)blockIdx.x * blockDim.x + threadIdx.x; i < total4; i += stride) {
        float4 v = f4[i];
        int c0 = (int)(i % (size_t)Cfq) * 4;
        size_t r = i / (size_t)Cfq;
        half2x2 h;
        h.a = __floats2half2_rn(v.x, v.y);
        h.b = __floats2half2_rn(v.z, v.w);
        *(half2x2*)(out + r * (size_t)ostride + coff + c0) = h;
    }
}

// ==========================================================================
extern "C" void kernel_launch(void* const* d_in, const int* in_sizes, int n_in,
                              void* d_out, int out_size)
{
    (void)in_sizes; (void)n_in; (void)out_size;

    const float* f0    = (const float*)d_in[0];
    const float* f1    = (const float*)d_in[1];
    const float* f2    = (const float*)d_in[2];
    const float* f3    = (const float*)d_in[3];
    const float* W_up2 = (const float*)d_in[4];
    const float* W_up1 = (const float*)d_in[5];
    const float* W_up0 = (const float*)d_in[6];
    const float* W_s0  = (const float*)d_in[7];
    const float* W_s1  = (const float*)d_in[8];
    const float* W_s2  = (const float*)d_in[9];
    const float* g_up2 = (const float*)d_in[10]; const float* b_up2 = (const float*)d_in[11];
    const float* g_up1 = (const float*)d_in[12]; const float* b_up1 = (const float*)d_in[13];
    const float* g_up0 = (const float*)d_in[14]; const float* b_up0 = (const float*)d_in[15];
    const float* g_s0  = (const float*)d_in[16]; const float* b_s0  = (const float*)d_in[17];
    const float* g_s1  = (const float*)d_in[18]; const float* b_s1  = (const float*)d_in[19];
    const float* g_s2  = (const float*)d_in[20]; const float* b_s2  = (const float*)d_in[21];
    const int* up2_in = (const int*)d_in[22]; const int* up2_out = (const int*)d_in[23];
    const int* up1_in = (const int*)d_in[24]; const int* up1_out = (const int*)d_in[25];
    const int* up0_in = (const int*)d_in[26]; const int* up0_out = (const int*)d_in[27];
    const int* sm0_in = (const int*)d_in[28]; const int* sm0_out = (const int*)d_in[29];
    const int* sm1_in = (const int*)d_in[30]; const int* sm1_out = (const int*)d_in[31];

    float *acc, *stats, *scale, *shift;
    __half *hA, *hB, *wth;
    cudaGetSymbolAddress((void**)&acc,   g_acc);
    cudaGetSymbolAddress((void**)&hA,    g_hA);
    cudaGetSymbolAddress((void**)&hB,    g_hB);
    cudaGetSymbolAddress((void**)&wth,   g_wth);
    cudaGetSymbolAddress((void**)&stats, g_stats);
    cudaGetSymbolAddress((void**)&scale, g_scale);
    cudaGetSymbolAddress((void**)&shift, g_shift);

    cudaFuncSetAttribute(mma_gs_kernel,
                         cudaFuncAttributeMaxDynamicSharedMemorySize, SMEM_DYN);

    const int N0 = 30000, N1 = 12000, N2 = 5000;
    const int K = 27;

    // --- transpose all weights into fp16 pool ---
    __half* wt_up2 = wth;
    __half* wt_up1 = wt_up2 + (size_t)27 * 128 * 128;
    __half* wt_up0 = wt_up1 + (size_t)27 * 192 * 192;
    __half* wt_s0  = wt_up0 + (size_t)27 * 224 * 224;
    __half* wt_s1  = wt_s0  + (size_t)27 * 240 * 512;
    __half* wt_s2  = wt_s1  + (size_t)27 * 512 * 512;

    auto tlaunch = [&](const float* W, __half* WT, int Cin, int Cout, int kk) {
        dim3 tg((Cout + 31) / 32, (Cin + 31) / 32, kk);
        transpose_kernel<<<tg, dim3(32, 8), 0, 0>>>(W, WT, Cin, Cout);
    };
    tlaunch(W_up2, wt_up2, 128, 128, K);
    tlaunch(W_up1, wt_up1, 192, 192, K);
    tlaunch(W_up0, wt_up0, 224, 224, K);
    tlaunch(W_s0,  wt_s0,  240, 512, K);
    tlaunch(W_s1,  wt_s1,  512, 512, K);
    tlaunch(W_s2,  wt_s2,  512, 512, 1);

    // f3 -> fp16 in hB (hB not written again until up1's output)
    cvt_kernel<<<ELTW_G, 256, 0, 0>>>((const float4*)f3, (half2x2*)hB, (size_t)2000 * 128 / 4);

    auto layer = [&](const __half* A, const __half* WT,
                     const int* ii, const int* oi,
                     int M, int Cin, int Cout, int Nout,
                     const float* gamma, const float* beta,
                     __half* outbuf, int ostride,       // fp16 output (or null for final)
                     float* foutbuf,                    // fp32 output (final layer)
                     const float* skip, int Cskip, int skip_N)
    {
        bool sparse = (oi != nullptr);
        float* dst = sparse ? acc : foutbuf;
        if (sparse)
            cudaMemsetAsync(acc, 0, (size_t)Nout * Cout * sizeof(float), 0);
        cudaMemsetAsync(stats, 0, 1024 * sizeof(float), 0);

        dim3 grid((M + 127) / 128, (Cout + 127) / 128, sparse ? K : 1);
        mma_gs_kernel<<<grid, 256, SMEM_DYN, 0>>>(A, WT, ii, oi, dst, M, Cin, Cout);

        size_t total4 = (size_t)Nout * Cout / 4;
        int Cq = Cout / 4;
        stats_kernel<<<STATS_G, 256, 2 * Cout * sizeof(float), 0>>>(
            (const float4*)dst, total4, Cq, stats);
        bnparam_kernel<<<2, 256, 0, 0>>>(stats, gamma, beta, Nout, Cout, scale, shift);
        if (outbuf) {
            bnapply_h_kernel<<<ELTW_G, 256, 0, 0>>>((const float4*)dst, total4, Cq,
                                                    ostride, scale, shift, outbuf);
            if (skip)
                copyskip_kernel<<<ELTW_G, 256, 0, 0>>>((const float4*)skip,
                                                       (size_t)skip_N * Cskip / 4,
                                                       Cskip / 4, ostride, Cout, outbuf);
        } else {
            bnapply_f_kernel<<<ELTW_G, 256, 0, 0>>>((float4*)dst, total4, Cq, scale, shift);
        }
    };

    // up2: f3(h) -> N2 (Cout 128), concat f2(64) -> hA[5000,192]
    layer(hB, wt_up2, up2_in, up2_out, 1600, 128, 128, N2, g_up2, b_up2, hA, 192, nullptr, f2, 64, N2);
    // up1: hA -> N1 (Cout 192), concat f1(32) -> hB[12000,224]
    layer(hA, wt_up1, up1_in, up1_out, 4000, 192, 192, N1, g_up1, b_up1, hB, 224, nullptr, f1, 32, N1);
    // up0: hB -> N0 (Cout 224), concat f0(16) -> hA[30000,240]
    layer(hB, wt_up0, up0_in, up0_out, 10000, 224, 224, N0, g_up0, b_up0, hA, 240, nullptr, f0, 16, N0);
    // s0: hA[30000,240] -> N0 (Cout 512) -> hB
    layer(hA, wt_s0, sm0_in, sm0_out, 10000, 240, 512, N0, g_s0, b_s0, hB, 512, nullptr, nullptr, 0, 0);
    // s1: hB -> N0 (Cout 512) -> hA
    layer(hB, wt_s1, sm1_in, sm1_out, 10000, 512, 512, N0, g_s1, b_s1, hA, 512, nullptr, nullptr, 0, 0);
    // s2: dense GEMM hA @ W_s2 -> d_out (fp32), BN+ReLU in place
    layer(hA, wt_s2, nullptr, nullptr, N0, 512, 512, N0, g_s2, b_s2, nullptr, 512, (float*)d_out, nullptr, 0, 0);
}

// round 16
// speedup vs baseline: 2.3002x; 1.0218x over previous
#include <cuda_runtime.h>
#include <cuda_fp16.h>
#include <cstdint>
#include <cstddef>

#define BN_EPS 1e-5f
#define HROW 40      // smem row stride in halfs (80 B, 16B-aligned)

// dynamic smem (bytes): [0,512) rowIdx; [512,+20480) As x2; [20992,+20480) Bs x2
#define OFF_AS 512
#define OFF_BS 20992
#define SMEM_DYN (20992 + 20480)

#define ELTW_G  1184   // grid for elementwise kernels
#define STATS_G 588    // 588*256 = 150528, divisible by Cq for Cq in {32,48,56,128}

// ======================= static scratch (no allocs) =======================
__device__ float  g_acc [30000 * 512];
__device__ __half g_hA  [30000 * 512];
__device__ __half g_hB  [30000 * 512];
__device__ __half g_wth [13450240];     // transposed fp16 weights pool
__device__ float  g_stats[1024];        // [0,512) sum, [512,1024) sumsq
__device__ float  g_scale[512];
__device__ float  g_shift[512];

struct half2x2 { __half2 a, b; };       // 8-byte packed store unit

// ======================= helpers =========================================
__device__ __forceinline__ uint32_t smem_u32(const void* p) {
    uint32_t a;
    asm("{ .reg .u64 t; cvta.to.shared.u64 t, %1; cvt.u32.u64 %0, t; }" : "=r"(a) : "l"(p));
    return a;
}
__device__ __forceinline__ void mma_f16(float* d, const uint32_t* a, const uint32_t* b) {
    asm volatile(
        "mma.sync.aligned.m16n8k16.row.col.f32.f16.f16.f32 "
        "{%0,%1,%2,%3}, {%4,%5,%6,%7}, {%8,%9}, {%0,%1,%2,%3};"
        : "+f"(d[0]), "+f"(d[1]), "+f"(d[2]), "+f"(d[3])
        : "r"(a[0]), "r"(a[1]), "r"(a[2]), "r"(a[3]), "r"(b[0]), "r"(b[1]));
}
__device__ __forceinline__ void red_add_v4(float* p, float a, float b, float c, float d) {
    asm volatile("red.global.add.v4.f32 [%0], {%1, %2, %3, %4};"
                 :: "l"(p), "f"(a), "f"(b), "f"(c), "f"(d) : "memory");
}
__device__ __forceinline__ void cp_async16(uint32_t dst, const void* src, int szvalid) {
    asm volatile("cp.async.cg.shared.global [%0], [%1], 16, %2;"
                 :: "r"(dst), "l"(src), "r"(szvalid) : "memory");
}
#define CP_COMMIT()  asm volatile("cp.async.commit_group;" ::: "memory")
#define CP_WAIT(n)   asm volatile("cp.async.wait_group %0;" :: "n"(n) : "memory")

// ======================= fp16 tensor-core gather-GEMM-scatter =============
// (unchanged — proven at 1468us, at the mma.sync tensor floor)
__global__ __launch_bounds__(256, 2) void mma_gs_kernel(
    const __half* __restrict__ A, const __half* __restrict__ WT,
    const int* __restrict__ in_idx, const int* __restrict__ out_idx,
    float* __restrict__ C, int M, int Cin, int Cout)
{
    extern __shared__ char sm[];
    int*      rowIdx = (int*)sm;
    uint32_t* AsW    = (uint32_t*)(sm + OFF_AS);
    uint32_t* BsW    = (uint32_t*)(sm + OFF_BS);
    const uint32_t bsU = smem_u32(sm) + OFF_BS;

    const int tid  = threadIdx.x;
    const int wid  = tid >> 5;
    const int lane = tid & 31;
    const int g8   = lane >> 2;
    const int t4   = lane & 3;

    const int k     = blockIdx.z;
    const int mBase = blockIdx.x * 128;
    const int n0    = blockIdx.y * 128;
    const __half* WTk = WT + (size_t)k * Cout * Cin;

    const int warpM = (wid >> 2) * 64;
    const int warpN = (wid & 3) * 32;

    if (tid < 128) {
        int g = mBase + tid;
        int ri = 0;
        if (g < M) ri = in_idx ? in_idx[(size_t)k * M + g] : g;
        rowIdx[tid] = ri;
    }
    __syncthreads();

    const __half* aptr[2];
    const __half* bptr[2];
    int bvalid[2];
#pragma unroll
    for (int s = 0; s < 2; ++s) {
        int gi = tid + s * 256;
        int row = gi >> 2, j = gi & 3;
        aptr[s] = A + (size_t)rowIdx[row] * Cin + 8 * j;
        int brow = n0 + row;
        bvalid[s] = (brow < Cout);
        bptr[s] = WTk + (size_t)(bvalid[s] ? brow : 0) * Cin + 8 * j;
    }

    float d[4][4][4];
#pragma unroll
    for (int mi = 0; mi < 4; mi++)
#pragma unroll
        for (int ni = 0; ni < 4; ni++)
#pragma unroll
            for (int r = 0; r < 4; r++) d[mi][ni][r] = 0.f;

    const int nc = (Cin + 31) >> 5;

    uint4 pav[2];
#pragma unroll
    for (int s = 0; s < 2; ++s) {
        int gi = tid + s * 256;
        int j = gi & 3;
        pav[s] = make_uint4(0u, 0u, 0u, 0u);
        if (8 * j < Cin) pav[s] = *(const uint4*)(aptr[s]);
    }
#pragma unroll
    for (int s = 0; s < 2; ++s) {
        int gi = tid + s * 256;
        int row = gi >> 2, j = gi & 3;
        int ok = (8 * j < Cin && bvalid[s]) ? 16 : 0;
        cp_async16(bsU + (uint32_t)(row * 80 + 16 * j), bptr[s], ok);
    }
    CP_COMMIT();

    for (int c = 0; c < nc; ++c) {
        const int st = c & 1;
        const int stoff = st * 128 * (HROW / 2);

#pragma unroll
        for (int s = 0; s < 2; ++s) {
            int gi = tid + s * 256;
            int row = gi >> 2, j = gi & 3;
            *(uint4*)&AsW[stoff + row * 20 + 4 * j] = pav[s];
        }

        if (c + 1 < nc) {
            const int c1 = (c + 1) << 5;
#pragma unroll
            for (int s = 0; s < 2; ++s) {
                int gi = tid + s * 256;
                int j = gi & 3;
                int col = c1 + 8 * j;
                pav[s] = make_uint4(0u, 0u, 0u, 0u);
                if (col < Cin) pav[s] = *(const uint4*)(aptr[s] + c1);
            }
        }

        CP_WAIT(0);
        __syncthreads();

        if (c + 1 < nc) {
            const int c1 = (c + 1) << 5;
#pragma unroll
            for (int s = 0; s < 2; ++s) {
                int gi = tid + s * 256;
                int row = gi >> 2, j = gi & 3;
                int ok = (c1 + 8 * j < Cin && bvalid[s]) ? 16 : 0;
                cp_async16(bsU + (uint32_t)((st ^ 1) * 10240 + row * 80 + 16 * j),
                           bptr[s] + c1, ok);
            }
            CP_COMMIT();
        }

        const uint32_t* AsB = AsW + stoff;
        const uint32_t* BsB = BsW + stoff;
#pragma unroll
        for (int kk = 0; kk < 2; ++kk) {
            const int kw = kk * 8;
            uint32_t a[4][4];
#pragma unroll
            for (int mi = 0; mi < 4; mi++) {
                int r = warpM + mi * 16 + g8;
                int w = r * 20 + kw + t4;
                a[mi][0] = AsB[w];
                a[mi][1] = AsB[w + 8 * 20];
                a[mi][2] = AsB[w + 4];
                a[mi][3] = AsB[w + 8 * 20 + 4];
            }
            uint32_t b[4][2];
#pragma unroll
            for (int ni = 0; ni < 4; ni++) {
                int n = warpN + ni * 8 + g8;
                int w = n * 20 + kw + t4;
                b[ni][0] = BsB[w];
                b[ni][1] = BsB[w + 4];
            }
#pragma unroll
            for (int mi = 0; mi < 4; mi++)
#pragma unroll
                for (int ni = 0; ni < 4; ni++)
                    mma_f16(d[mi][ni], a[mi], b[ni]);
        }
    }

#pragma unroll
    for (int mi = 0; mi < 4; mi++) {
        int r0 = mBase + warpM + mi * 16 + g8;
#pragma unroll
        for (int half = 0; half < 2; half++) {
            int rr = r0 + half * 8;
            size_t orow = 0;
            if (rr < M)
                orow = out_idx ? (size_t)out_idx[(size_t)k * M + rr] : (size_t)rr;
            float* crow = C + orow * Cout;
#pragma unroll
            for (int ni = 0; ni < 4; ni++) {
                float v0 = d[mi][ni][half * 2 + 0];
                float v1 = d[mi][ni][half * 2 + 1];
                float p0 = __shfl_xor_sync(0xffffffffu, v0, 1);
                float p1 = __shfl_xor_sync(0xffffffffu, v1, 1);
                if (rr < M && (t4 & 1) == 0) {
                    int col = n0 + warpN + ni * 8 + (t4 << 1);
                    if (col < Cout) {
                        if (out_idx) red_add_v4(crow + col, v0, v1, p0, p1);
                        else *(float4*)(crow + col) = make_float4(v0, v1, p0, p1);
                    }
                }
            }
        }
    }
}

// ===== weight transpose [K][Cin][Cout] -> [K][Cout][Cin], fp16, half2 out =
// Store phase emits __half2 covering two consecutive output rows (R even).
__global__ void transpose_kernel(const float* __restrict__ in, __half* __restrict__ out,
                                 int R, int Ccol)
{
    __shared__ float t[32][33];
    const size_t koff = (size_t)blockIdx.z * R * Ccol;
    const float* ink = in + koff;
    __half* outk = out + koff;
    int c0 = blockIdx.x * 32, r0 = blockIdx.y * 32;
    int tx = threadIdx.x, ty = threadIdx.y;   // block (32, 8)
    for (int i = ty; i < 32; i += 8) {
        int r = r0 + i, c = c0 + tx;
        t[i][tx] = (r < R && c < Ccol) ? ink[(size_t)r * Ccol + c] : 0.f;
    }
    __syncthreads();
    int sid = ty * 32 + tx;
#pragma unroll
    for (int j = 0; j < 2; ++j) {
        int idx = sid + 256 * j;        // 0..511
        int ci  = idx >> 4;             // 0..31 (out column within tile)
        int rp  = idx & 15;             // half2 pair index
        int cc  = c0 + ci;
        int rr  = r0 + 2 * rp;
        if (cc < Ccol && rr < R) {
            __half2 v = __floats2half2_rn(t[2 * rp][ci], t[2 * rp + 1][ci]);
            *(__half2*)(outk + (size_t)cc * R + rr) = v;
        }
    }
}

// ============ f32 -> f16 vectorized convert (n4 = n/4 float4s) ===========
__global__ void cvt_kernel(const float4* __restrict__ in, half2x2* __restrict__ out, size_t n4)
{
    size_t stride = (size_t)gridDim.x * blockDim.x;
    for (size_t i = (size_t)blockIdx.x * blockDim.x + threadIdx.x; i < n4; i += stride) {
        float4 v = in[i];
        half2x2 o;
        o.a = __floats2half2_rn(v.x, v.y);
        o.b = __floats2half2_rn(v.z, v.w);
        out[i] = o;
    }
}

// ==== stats: register accumulation (fixed channels) + shared flush =======
// REQUIRES: (gridDim.x * blockDim.x) % Cq == 0  -> channels loop-invariant.
__global__ void stats_kernel(const float4* __restrict__ x4, size_t total4, int Cq,
                             float* __restrict__ stats /* [0,C) sum, [512,512+C) sq */)
{
    extern __shared__ float s[];  // 2*C floats
    const int C = Cq * 4;
    size_t idx0   = (size_t)blockIdx.x * blockDim.x + threadIdx.x;
    size_t stride = (size_t)gridDim.x * blockDim.x;
    float s0 = 0.f, s1 = 0.f, s2 = 0.f, s3 = 0.f;
    float q0 = 0.f, q1 = 0.f, q2 = 0.f, q3 = 0.f;
    for (size_t i = idx0; i < total4; i += stride) {
        float4 v = x4[i];
        s0 += v.x; q0 += v.x * v.x;
        s1 += v.y; q1 += v.y * v.y;
        s2 += v.z; q2 += v.z * v.z;
        s3 += v.w; q3 += v.w * v.w;
    }
    for (int i = threadIdx.x; i < 2 * C; i += blockDim.x) s[i] = 0.f;
    __syncthreads();
    int c0 = (int)(idx0 % (size_t)Cq) * 4;
    atomicAdd(&s[c0 + 0], s0);
    atomicAdd(&s[c0 + 1], s1);
    atomicAdd(&s[c0 + 2], s2);
    atomicAdd(&s[c0 + 3], s3);
    atomicAdd(&s[C + c0 + 0], q0);
    atomicAdd(&s[C + c0 + 1], q1);
    atomicAdd(&s[C + c0 + 2], q2);
    atomicAdd(&s[C + c0 + 3], q3);
    __syncthreads();
    for (int c = threadIdx.x; c < C; c += blockDim.x) {
        atomicAdd(&stats[c], s[c]);
        atomicAdd(&stats[512 + c], s[C + c]);
    }
}

// bnparam also RESETS stats to zero for the next layer (saves a memset launch)
__global__ void bnparam_kernel(float* __restrict__ stats,
                               const float* __restrict__ gamma, const float* __restrict__ beta,
                               int N, int C,
                               float* __restrict__ scale, float* __restrict__ shift)
{
    int c = blockIdx.x * blockDim.x + threadIdx.x;
    if (c < 512) {
        float sm = stats[c];
        float sq = stats[512 + c];
        if (c < C) {
            float invN = 1.f / (float)N;
            float m = sm * invN;
            float v = sq * invN - m * m;
            float sc = gamma[c] * rsqrtf(v + BN_EPS);
            scale[c] = sc;
            shift[c] = beta[c] - m * sc;
        }
        stats[c] = 0.f;
        stats[512 + c] = 0.f;
    }
}

// normalize+ReLU -> fp16 concat buffer, PLUS fused skip copy (f32->f16)
__global__ void bnapply_h_kernel(const float4* __restrict__ x4, size_t total4, int Cq,
                                 int ostride,
                                 const float* __restrict__ scale, const float* __restrict__ shift,
                                 __half* __restrict__ out,
                                 const float4* __restrict__ skip4, size_t stotal4,
                                 int Cfq, int coff)
{
    size_t stride = (size_t)gridDim.x * blockDim.x;
    size_t tid0   = (size_t)blockIdx.x * blockDim.x + threadIdx.x;
    for (size_t i = tid0; i < total4; i += stride) {
        float4 v = x4[i];
        int cq = (int)(i % (size_t)Cq);
        size_t r = i / (size_t)Cq;
        int c0 = cq * 4;
        float o0 = fmaxf(fmaf(v.x, scale[c0 + 0], shift[c0 + 0]), 0.f);
        float o1 = fmaxf(fmaf(v.y, scale[c0 + 1], shift[c0 + 1]), 0.f);
        float o2 = fmaxf(fmaf(v.z, scale[c0 + 2], shift[c0 + 2]), 0.f);
        float o3 = fmaxf(fmaf(v.w, scale[c0 + 3], shift[c0 + 3]), 0.f);
        half2x2 h;
        h.a = __floats2half2_rn(o0, o1);
        h.b = __floats2half2_rn(o2, o3);
        *(half2x2*)(out + r * (size_t)ostride + c0) = h;
    }
    if (skip4) {
        for (size_t i = tid0; i < stotal4; i += stride) {
            float4 v = skip4[i];
            int c0 = (int)(i % (size_t)Cfq) * 4;
            size_t r = i / (size_t)Cfq;
            half2x2 h;
            h.a = __floats2half2_rn(v.x, v.y);
            h.b = __floats2half2_rn(v.z, v.w);
            *(half2x2*)(out + r * (size_t)ostride + coff + c0) = h;
        }
    }
}

// final layer: normalize+ReLU in place (fp32), vectorized
__global__ void bnapply_f_kernel(float4* __restrict__ x4, size_t total4, int Cq,
                                 const float* __restrict__ scale, const float* __restrict__ shift)
{
    size_t stride = (size_t)gridDim.x * blockDim.x;
    for (size_t i = (size_t)blockIdx.x * blockDim.x + threadIdx.x; i < total4; i += stride) {
        float4 v = x4[i];
        int c0 = (int)(i % (size_t)Cq) * 4;
        v.x = fmaxf(fmaf(v.x, scale[c0 + 0], shift[c0 + 0]), 0.f);
        v.y = fmaxf(fmaf(v.y, scale[c0 + 1], shift[c0 + 1]), 0.f);
        v.z = fmaxf(fmaf(v.z, scale[c0 + 2], shift[c0 + 2]), 0.f);
        v.w = fmaxf(fmaf(v.w, scale[c0 + 3], shift[c0 + 3]), 0.f);
        x4[i] = v;
    }
}

// ==========================================================================
extern "C" void kernel_launch(void* const* d_in, const int* in_sizes, int n_in,
                              void* d_out, int out_size)
{
    (void)in_sizes; (void)n_in; (void)out_size;

    const float* f0    = (const float*)d_in[0];
    const float* f1    = (const float*)d_in[1];
    const float* f2    = (const float*)d_in[2];
    const float* f3    = (const float*)d_in[3];
    const float* W_up2 = (const float*)d_in[4];
    const float* W_up1 = (const float*)d_in[5];
    const float* W_up0 = (const float*)d_in[6];
    const float* W_s0  = (const float*)d_in[7];
    const float* W_s1  = (const float*)d_in[8];
    const float* W_s2  = (const float*)d_in[9];
    const float* g_up2 = (const float*)d_in[10]; const float* b_up2 = (const float*)d_in[11];
    const float* g_up1 = (const float*)d_in[12]; const float* b_up1 = (const float*)d_in[13];
    const float* g_up0 = (const float*)d_in[14]; const float* b_up0 = (const float*)d_in[15];
    const float* g_s0  = (const float*)d_in[16]; const float* b_s0  = (const float*)d_in[17];
    const float* g_s1  = (const float*)d_in[18]; const float* b_s1  = (const float*)d_in[19];
    const float* g_s2  = (const float*)d_in[20]; const float* b_s2  = (const float*)d_in[21];
    const int* up2_in = (const int*)d_in[22]; const int* up2_out = (const int*)d_in[23];
    const int* up1_in = (const int*)d_in[24]; const int* up1_out = (const int*)d_in[25];
    const int* up0_in = (const int*)d_in[26]; const int* up0_out = (const int*)d_in[27];
    const int* sm0_in = (const int*)d_in[28]; const int* sm0_out = (const int*)d_in[29];
    const int* sm1_in = (const int*)d_in[30]; const int* sm1_out = (const int*)d_in[31];

    float *acc, *stats, *scale, *shift;
    __half *hA, *hB, *wth;
    cudaGetSymbolAddress((void**)&acc,   g_acc);
    cudaGetSymbolAddress((void**)&hA,    g_hA);
    cudaGetSymbolAddress((void**)&hB,    g_hB);
    cudaGetSymbolAddress((void**)&wth,   g_wth);
    cudaGetSymbolAddress((void**)&stats, g_stats);
    cudaGetSymbolAddress((void**)&scale, g_scale);
    cudaGetSymbolAddress((void**)&shift, g_shift);

    cudaFuncSetAttribute(mma_gs_kernel,
                         cudaFuncAttributeMaxDynamicSharedMemorySize, SMEM_DYN);

    const int N0 = 30000, N1 = 12000, N2 = 5000;
    const int K = 27;

    // --- transpose all weights into fp16 pool ---
    __half* wt_up2 = wth;
    __half* wt_up1 = wt_up2 + (size_t)27 * 128 * 128;
    __half* wt_up0 = wt_up1 + (size_t)27 * 192 * 192;
    __half* wt_s0  = wt_up0 + (size_t)27 * 224 * 224;
    __half* wt_s1  = wt_s0  + (size_t)27 * 240 * 512;
    __half* wt_s2  = wt_s1  + (size_t)27 * 512 * 512;

    auto tlaunch = [&](const float* W, __half* WT, int Cin, int Cout, int kk) {
        dim3 tg((Cout + 31) / 32, (Cin + 31) / 32, kk);
        transpose_kernel<<<tg, dim3(32, 8), 0, 0>>>(W, WT, Cin, Cout);
    };
    tlaunch(W_up2, wt_up2, 128, 128, K);
    tlaunch(W_up1, wt_up1, 192, 192, K);
    tlaunch(W_up0, wt_up0, 224, 224, K);
    tlaunch(W_s0,  wt_s0,  240, 512, K);
    tlaunch(W_s1,  wt_s1,  512, 512, K);
    tlaunch(W_s2,  wt_s2,  512, 512, 1);

    // f3 -> fp16 in hB; one upfront stats clear (bnparam re-clears each layer)
    cvt_kernel<<<ELTW_G, 256, 0, 0>>>((const float4*)f3, (half2x2*)hB, (size_t)2000 * 128 / 4);
    cudaMemsetAsync(stats, 0, 1024 * sizeof(float), 0);

    auto layer = [&](const __half* A, const __half* WT,
                     const int* ii, const int* oi,
                     int M, int Cin, int Cout, int Nout,
                     const float* gamma, const float* beta,
                     __half* outbuf, int ostride,       // fp16 output (or null for final)
                     float* foutbuf,                    // fp32 output (final layer)
                     const float* skip, int Cskip, int skip_N)
    {
        bool sparse = (oi != nullptr);
        float* dst = sparse ? acc : foutbuf;
        if (sparse)
            cudaMemsetAsync(acc, 0, (size_t)Nout * Cout * sizeof(float), 0);

        dim3 grid((M + 127) / 128, (Cout + 127) / 128, sparse ? K : 1);
        mma_gs_kernel<<<grid, 256, SMEM_DYN, 0>>>(A, WT, ii, oi, dst, M, Cin, Cout);

        size_t total4 = (size_t)Nout * Cout / 4;
        int Cq = Cout / 4;
        stats_kernel<<<STATS_G, 256, 2 * Cout * sizeof(float), 0>>>(
            (const float4*)dst, total4, Cq, stats);
        bnparam_kernel<<<2, 256, 0, 0>>>(stats, gamma, beta, Nout, Cout, scale, shift);
        if (outbuf) {
            bnapply_h_kernel<<<ELTW_G, 256, 0, 0>>>(
                (const float4*)dst, total4, Cq, ostride, scale, shift, outbuf,
                (const float4*)skip, skip ? (size_t)skip_N * Cskip / 4 : 0,
                skip ? Cskip / 4 : 1, Cout);
        } else {
            bnapply_f_kernel<<<ELTW_G, 256, 0, 0>>>((float4*)dst, total4, Cq, scale, shift);
        }
    };

    // up2: f3(h) -> N2 (Cout 128), concat f2(64) -> hA[5000,192]
    layer(hB, wt_up2, up2_in, up2_out, 1600, 128, 128, N2, g_up2, b_up2, hA, 192, nullptr, f2, 64, N2);
    // up1: hA -> N1 (Cout 192), concat f1(32) -> hB[12000,224]
    layer(hA, wt_up1, up1_in, up1_out, 4000, 192, 192, N1, g_up1, b_up1, hB, 224, nullptr, f1, 32, N1);
    // up0: hB -> N0 (Cout 224), concat f0(16) -> hA[30000,240]
    layer(hB, wt_up0, up0_in, up0_out, 10000, 224, 224, N0, g_up0, b_up0, hA, 240, nullptr, f0, 16, N0);
    // s0: hA[30000,240] -> N0 (Cout 512) -> hB
    layer(hA, wt_s0, sm0_in, sm0_out, 10000, 240, 512, N0, g_s0, b_s0, hB, 512, nullptr, nullptr, 0, 0);
    // s1: hB -> N0 (Cout 512) -> hA
    layer(hB, wt_s1, sm1_in, sm1_out, 10000, 512, 512, N0, g_s1, b_s1, hA, 512, nullptr, nullptr, 0, 0);
    // s2: dense GEMM hA @ W_s2 -> d_out (fp32), BN+ReLU in place
    layer(hA, wt_s2, nullptr, nullptr, N0, 512, 512, N0, g_s2, b_s2, nullptr, 512, (float*)d_out, nullptr, 0, 0);
}